// round 7
// baseline (speedup 1.0000x reference)
#include <cuda_runtime.h>

#define IMG_H 1080
#define IMG_W 1920
#define PLANE (IMG_H * IMG_W)

// JPEG-style base quant table (row-major 8x8)
__constant__ float c_qbase[64] = {
    16, 11, 10, 16, 24, 40, 51, 61,
    12, 12, 14, 19, 26, 58, 60, 55,
    14, 13, 16, 24, 40, 57, 69, 56,
    14, 17, 22, 29, 51, 87, 80, 62,
    18, 22, 37, 56, 68, 109, 103, 77,
    24, 35, 55, 64, 81, 104, 113, 92,
    49, 64, 78, 87, 103, 121, 120, 101,
    72, 92, 95, 98, 112, 100, 103, 99
};

// DCT-II basis constants (immediate operands in SASS)
#define H1 0.4903926402016152f
#define H2 0.4619397662556434f
#define H3 0.4157348061512726f
#define H4 0.3535533905932738f
#define H5 0.2777851165098011f
#define H6 0.1913417161825449f
#define H7 0.0975451610080641f

// Forward 8-pt DCT via even/odd butterfly: w[k] = sum_i BAS[k][i] * a[i]
__device__ __forceinline__ void dct8(const float a[8], float w[8]) {
    float s0 = a[0] + a[7], s1 = a[1] + a[6], s2 = a[2] + a[5], s3 = a[3] + a[4];
    float d0 = a[0] - a[7], d1 = a[1] - a[6], d2 = a[2] - a[5], d3 = a[3] - a[4];
    float e0 = s0 + s3, e1 = s1 + s2, f0 = s0 - s3, f1 = s1 - s2;
    w[0] = H4 * (e0 + e1);
    w[4] = H4 * (e0 - e1);
    w[2] = fmaf(H2, f0,  H6 * f1);
    w[6] = fmaf(H6, f0, -H2 * f1);
    w[1] = fmaf(H1, d0, fmaf( H3, d1, fmaf( H5, d2,  H7 * d3)));
    w[3] = fmaf(H3, d0, fmaf(-H7, d1, fmaf(-H1, d2, -H5 * d3)));
    w[5] = fmaf(H5, d0, fmaf(-H1, d1, fmaf( H7, d2,  H3 * d3)));
    w[7] = fmaf(H7, d0, fmaf(-H5, d1, fmaf( H3, d2, -H1 * d3)));
}

// Inverse 8-pt DCT via butterfly: r[n] = sum_k BAS[k][n] * c[k]
__device__ __forceinline__ void idct8(const float c[8], float r[8]) {
    float p = H4 * (c[0] + c[4]);
    float m = H4 * (c[0] - c[4]);
    float u = fmaf(H2, c[2],  H6 * c[6]);
    float v = fmaf(H6, c[2], -H2 * c[6]);
    float E0 = p + u, E1 = m + v, E2 = m - v, E3 = p - u;
    float O0 = fmaf(H1, c[1], fmaf( H3, c[3], fmaf( H5, c[5],  H7 * c[7])));
    float O1 = fmaf(H3, c[1], fmaf(-H7, c[3], fmaf(-H1, c[5], -H5 * c[7])));
    float O2 = fmaf(H5, c[1], fmaf(-H1, c[3], fmaf( H7, c[5],  H3 * c[7])));
    float O3 = fmaf(H7, c[1], fmaf(-H5, c[3], fmaf( H3, c[5], -H1 * c[7])));
    r[0] = E0 + O0;  r[7] = E0 - O0;
    r[1] = E1 + O1;  r[6] = E1 - O1;
    r[2] = E2 + O2;  r[5] = E2 - O2;
    r[3] = E3 + O3;  r[4] = E3 - O3;
}

__global__ __launch_bounds__(128, 10)
void h264_dct_kernel(const float* __restrict__ x, float* __restrict__ out) {
    // CTA: 128 threads, strip = 8 rows x 128 cols = 16 8x8 blocks.
    // Thread t owns one 8-pixel column; bgr stay in registers. All 8x8
    // transpose dependencies live inside 8-lane groups (8 | 32), so the
    // transposes need only __syncwarp() -> warps free-run (no phase lockstep).
    // The single CTA-wide barrier is right after the quant-table init.
    __shared__ float s1[8][129];
    __shared__ float s2[8][129];
    __shared__ float sQ[8][9];    // quant step
    __shared__ float sRQ[8][9];   // 1 / (q + 1e-8)

    const int t = threadIdx.x;
    if (t < 64) {
        int k = t >> 3, u = t & 7;
        // QF=28 >= 25 -> scale = 144 ; q = max(base*144/50, 1)
        float q = fmaxf((c_qbase[t] * 144.0f) / 50.0f, 1.0f);
        sQ[k][u]  = q;
        sRQ[k][u] = 1.0f / (q + 1e-8f);
    }
    __syncthreads();   // only CTA-wide barrier: publish sQ/sRQ before use

    const int g = t >> 3;         // 8-lane group (block) index within strip
    const int l = t & 7;          // lane within block
    const int col = blockIdx.x * 128 + t;
    const size_t base = (size_t)blockIdx.z * (3 * (size_t)PLANE)
                      + (size_t)(blockIdx.y * 8) * IMG_W + col;

    float vb[8], vg[8], vr[8], a[8], w[8];

    // Load BGR once (registers), form luma column.
    #pragma unroll
    for (int i = 0; i < 8; ++i) {
        size_t p = base + (size_t)i * IMG_W;
        vb[i] = x[p];
        vg[i] = x[p + PLANE];
        vr[i] = x[p + 2 * PLANE];
        a[i]  = 0.114f * vb[i] + 0.587f * vg[i] + 0.299f * vr[i];
    }

    // Vertical DCT
    dct8(a, w);

    // Transpose 1: intra-warp only (each warp touches its own 32 columns)
    #pragma unroll
    for (int k = 0; k < 8; ++k) s1[k][t] = w[k];
    __syncwarp();
    #pragma unroll
    for (int j = 0; j < 8; ++j) a[j] = s1[l][(g << 3) + j];

    // Horizontal DCT + quantize (round-half-even; reciprocal multiply)
    dct8(a, w);
    float cq[8];
    #pragma unroll
    for (int u = 0; u < 8; ++u)
        cq[u] = rintf(w[u] * sRQ[l][u]) * sQ[l][u];

    // Horizontal IDCT
    idct8(cq, w);

    // Transpose 2: intra-warp only (separate buffer -> no WAR hazard)
    #pragma unroll
    for (int b = 0; b < 8; ++b) s2[l][(g << 3) + b] = w[b];
    __syncwarp();
    #pragma unroll
    for (int i = 0; i < 8; ++i) a[i] = s2[i][t];

    // Vertical IDCT
    float rec[8];
    idct8(a, rec);

    // Epilogue: delta redistribution from register-resident bgr.
    #pragma unroll
    for (int i = 0; i < 8; ++i) {
        float yv = 0.114f * vb[i] + 0.587f * vg[i] + 0.299f * vr[i];
        float yd = rec[i] - yv;
        size_t p = base + (size_t)i * IMG_W;
        out[p]             = fminf(fmaxf(vb[i] + 0.114f * yd, 0.0f), 255.0f);
        out[p + PLANE]     = fminf(fmaxf(vg[i] + 0.587f * yd, 0.0f), 255.0f);
        out[p + 2 * PLANE] = fminf(fmaxf(vr[i] + 0.299f * yd, 0.0f), 255.0f);
    }
}

extern "C" void kernel_launch(void* const* d_in, const int* in_sizes, int n_in,
                              void* d_out, int out_size) {
    const float* x = (const float*)d_in[0];
    float* out = (float*)d_out;

    int B = in_sizes[0] / (3 * PLANE);

    dim3 block(128, 1, 1);
    dim3 grid(IMG_W / 128, IMG_H / 8, B);   // 15 x 135 x B
    h264_dct_kernel<<<grid, block>>>(x, out);
}

// round 8
// speedup vs baseline: 1.0886x; 1.0886x over previous
#include <cuda_runtime.h>

#define IMG_H 1080
#define IMG_W 1920
#define PLANE (IMG_H * IMG_W)
#define SX 15          // strips across (1920/128)
#define SY 135         // strips down  (1080/8)

// JPEG-style base quant table (row-major 8x8)
__constant__ float c_qbase[64] = {
    16, 11, 10, 16, 24, 40, 51, 61,
    12, 12, 14, 19, 26, 58, 60, 55,
    14, 13, 16, 24, 40, 57, 69, 56,
    14, 17, 22, 29, 51, 87, 80, 62,
    18, 22, 37, 56, 68, 109, 103, 77,
    24, 35, 55, 64, 81, 104, 113, 92,
    49, 64, 78, 87, 103, 121, 120, 101,
    72, 92, 95, 98, 112, 100, 103, 99
};

// DCT-II basis constants (immediate operands in SASS)
#define H1 0.4903926402016152f
#define H2 0.4619397662556434f
#define H3 0.4157348061512726f
#define H4 0.3535533905932738f
#define H5 0.2777851165098011f
#define H6 0.1913417161825449f
#define H7 0.0975451610080641f

// Forward 8-pt DCT via even/odd butterfly: w[k] = sum_i BAS[k][i] * a[i]
__device__ __forceinline__ void dct8(const float a[8], float w[8]) {
    float s0 = a[0] + a[7], s1 = a[1] + a[6], s2 = a[2] + a[5], s3 = a[3] + a[4];
    float d0 = a[0] - a[7], d1 = a[1] - a[6], d2 = a[2] - a[5], d3 = a[3] - a[4];
    float e0 = s0 + s3, e1 = s1 + s2, f0 = s0 - s3, f1 = s1 - s2;
    w[0] = H4 * (e0 + e1);
    w[4] = H4 * (e0 - e1);
    w[2] = fmaf(H2, f0,  H6 * f1);
    w[6] = fmaf(H6, f0, -H2 * f1);
    w[1] = fmaf(H1, d0, fmaf( H3, d1, fmaf( H5, d2,  H7 * d3)));
    w[3] = fmaf(H3, d0, fmaf(-H7, d1, fmaf(-H1, d2, -H5 * d3)));
    w[5] = fmaf(H5, d0, fmaf(-H1, d1, fmaf( H7, d2,  H3 * d3)));
    w[7] = fmaf(H7, d0, fmaf(-H5, d1, fmaf( H3, d2, -H1 * d3)));
}

// Inverse 8-pt DCT via butterfly: r[n] = sum_k BAS[k][n] * c[k]
__device__ __forceinline__ void idct8(const float c[8], float r[8]) {
    float p = H4 * (c[0] + c[4]);
    float m = H4 * (c[0] - c[4]);
    float u = fmaf(H2, c[2],  H6 * c[6]);
    float v = fmaf(H6, c[2], -H2 * c[6]);
    float E0 = p + u, E1 = m + v, E2 = m - v, E3 = p - u;
    float O0 = fmaf(H1, c[1], fmaf( H3, c[3], fmaf( H5, c[5],  H7 * c[7])));
    float O1 = fmaf(H3, c[1], fmaf(-H7, c[3], fmaf(-H1, c[5], -H5 * c[7])));
    float O2 = fmaf(H5, c[1], fmaf(-H1, c[3], fmaf( H7, c[5],  H3 * c[7])));
    float O3 = fmaf(H7, c[1], fmaf(-H5, c[3], fmaf( H3, c[5], -H1 * c[7])));
    r[0] = E0 + O0;  r[7] = E0 - O0;
    r[1] = E1 + O1;  r[6] = E1 - O1;
    r[2] = E2 + O2;  r[5] = E2 - O2;
    r[3] = E3 + O3;  r[4] = E3 - O3;
}

__global__ __launch_bounds__(128, 10)
void h264_dct_kernel(const float* __restrict__ x, float* __restrict__ out,
                     int nStrips) {
    // Persistent grid-stride kernel: one resident wave of CTAs, each looping
    // over 8x128 strips (16 8x8 blocks each). Thread t owns one 8-pixel
    // column; bgr stay in registers. Butterfly transforms in registers;
    // smem only for two conflict-free 8x8 transposes (2 CTA barriers/strip).
    // Cross-iteration smem hazard: s1-reads of iter i precede barrier #2 of
    // iter i, which precedes s1-writes of iter i+1 -> safe with 2 barriers.
    __shared__ float s1[8][129];
    __shared__ float s2[8][129];
    __shared__ float sQ[8][9];    // quant step
    __shared__ float sRQ[8][9];   // 1 / (q + 1e-8)

    const int t = threadIdx.x;
    if (t < 64) {
        int k = t >> 3, u = t & 7;
        // QF=28 >= 25 -> scale = 144 ; q = max(base*144/50, 1)
        float q = fmaxf((c_qbase[t] * 144.0f) / 50.0f, 1.0f);
        sQ[k][u]  = q;
        sRQ[k][u] = 1.0f / (q + 1e-8f);
    }
    __syncthreads();

    const int g = t >> 3;         // block index within strip
    const int l = t & 7;          // lane within block

    for (int s = blockIdx.x; s < nStrips; s += gridDim.x) {
        const int sx   = s % SX;
        const int rest = s / SX;
        const int sy   = rest % SY;
        const int sb   = rest / SY;

        const size_t base = (size_t)sb * (3 * (size_t)PLANE)
                          + (size_t)(sy * 8) * IMG_W + sx * 128 + t;

        float vb[8], vg[8], vr[8], a[8], w[8];

        // Load BGR once (registers), form luma column.
        #pragma unroll
        for (int i = 0; i < 8; ++i) {
            size_t p = base + (size_t)i * IMG_W;
            vb[i] = x[p];
            vg[i] = x[p + PLANE];
            vr[i] = x[p + 2 * PLANE];
            a[i]  = 0.114f * vb[i] + 0.587f * vg[i] + 0.299f * vr[i];
        }

        // Vertical DCT
        dct8(a, w);

        // Transpose 1: thread -> owns row l of block g (bank-conflict-free)
        #pragma unroll
        for (int k = 0; k < 8; ++k) s1[k][t] = w[k];
        __syncthreads();
        #pragma unroll
        for (int j = 0; j < 8; ++j) a[j] = s1[l][(g << 3) + j];

        // Horizontal DCT + quantize (round-half-even; reciprocal multiply)
        dct8(a, w);
        float cq[8];
        #pragma unroll
        for (int u = 0; u < 8; ++u)
            cq[u] = rintf(w[u] * sRQ[l][u]) * sQ[l][u];

        // Horizontal IDCT
        idct8(cq, w);

        // Transpose 2 (separate buffer -> single barrier)
        #pragma unroll
        for (int b = 0; b < 8; ++b) s2[l][(g << 3) + b] = w[b];
        __syncthreads();
        #pragma unroll
        for (int i = 0; i < 8; ++i) a[i] = s2[i][t];

        // Vertical IDCT
        float rec[8];
        idct8(a, rec);

        // Epilogue: delta redistribution from register-resident bgr.
        #pragma unroll
        for (int i = 0; i < 8; ++i) {
            float yv = 0.114f * vb[i] + 0.587f * vg[i] + 0.299f * vr[i];
            float yd = rec[i] - yv;
            size_t p = base + (size_t)i * IMG_W;
            out[p]             = fminf(fmaxf(vb[i] + 0.114f * yd, 0.0f), 255.0f);
            out[p + PLANE]     = fminf(fmaxf(vg[i] + 0.587f * yd, 0.0f), 255.0f);
            out[p + 2 * PLANE] = fminf(fmaxf(vr[i] + 0.299f * yd, 0.0f), 255.0f);
        }
    }
}

extern "C" void kernel_launch(void* const* d_in, const int* in_sizes, int n_in,
                              void* d_out, int out_size) {
    const float* x = (const float*)d_in[0];
    float* out = (float*)d_out;

    int B = in_sizes[0] / (3 * PLANE);
    int nStrips = SX * SY * B;

    // One resident wave: 152 SMs x 10 CTAs/SM
    int nCTA = 1520;
    if (nCTA > nStrips) nCTA = nStrips;

    dim3 block(128, 1, 1);
    dim3 grid(nCTA, 1, 1);
    h264_dct_kernel<<<grid, block>>>(x, out, nStrips);
}

// round 9
// speedup vs baseline: 1.1826x; 1.0864x over previous
#include <cuda_runtime.h>

#define IMG_H 1080
#define IMG_W 1920
#define PLANE (IMG_H * IMG_W)

// JPEG-style base quant table (row-major 8x8)
__constant__ float c_qbase[64] = {
    16, 11, 10, 16, 24, 40, 51, 61,
    12, 12, 14, 19, 26, 58, 60, 55,
    14, 13, 16, 24, 40, 57, 69, 56,
    14, 17, 22, 29, 51, 87, 80, 62,
    18, 22, 37, 56, 68, 109, 103, 77,
    24, 35, 55, 64, 81, 104, 113, 92,
    49, 64, 78, 87, 103, 121, 120, 101,
    72, 92, 95, 98, 112, 100, 103, 99
};

// DCT-II basis constants (immediate operands in SASS)
#define H1 0.4903926402016152f
#define H2 0.4619397662556434f
#define H3 0.4157348061512726f
#define H4 0.3535533905932738f
#define H5 0.2777851165098011f
#define H6 0.1913417161825449f
#define H7 0.0975451610080641f

// Forward 8-pt DCT via even/odd butterfly: w[k] = sum_i BAS[k][i] * a[i]
__device__ __forceinline__ void dct8(const float a[8], float w[8]) {
    float s0 = a[0] + a[7], s1 = a[1] + a[6], s2 = a[2] + a[5], s3 = a[3] + a[4];
    float d0 = a[0] - a[7], d1 = a[1] - a[6], d2 = a[2] - a[5], d3 = a[3] - a[4];
    float e0 = s0 + s3, e1 = s1 + s2, f0 = s0 - s3, f1 = s1 - s2;
    w[0] = H4 * (e0 + e1);
    w[4] = H4 * (e0 - e1);
    w[2] = fmaf(H2, f0,  H6 * f1);
    w[6] = fmaf(H6, f0, -H2 * f1);
    w[1] = fmaf(H1, d0, fmaf( H3, d1, fmaf( H5, d2,  H7 * d3)));
    w[3] = fmaf(H3, d0, fmaf(-H7, d1, fmaf(-H1, d2, -H5 * d3)));
    w[5] = fmaf(H5, d0, fmaf(-H1, d1, fmaf( H7, d2,  H3 * d3)));
    w[7] = fmaf(H7, d0, fmaf(-H5, d1, fmaf( H3, d2, -H1 * d3)));
}

// Inverse 8-pt DCT via butterfly: r[n] = sum_k BAS[k][n] * c[k]
__device__ __forceinline__ void idct8(const float c[8], float r[8]) {
    float p = H4 * (c[0] + c[4]);
    float m = H4 * (c[0] - c[4]);
    float u = fmaf(H2, c[2],  H6 * c[6]);
    float v = fmaf(H6, c[2], -H2 * c[6]);
    float E0 = p + u, E1 = m + v, E2 = m - v, E3 = p - u;
    float O0 = fmaf(H1, c[1], fmaf( H3, c[3], fmaf( H5, c[5],  H7 * c[7])));
    float O1 = fmaf(H3, c[1], fmaf(-H7, c[3], fmaf(-H1, c[5], -H5 * c[7])));
    float O2 = fmaf(H5, c[1], fmaf(-H1, c[3], fmaf( H7, c[5],  H3 * c[7])));
    float O3 = fmaf(H7, c[1], fmaf(-H5, c[3], fmaf( H3, c[5], -H1 * c[7])));
    r[0] = E0 + O0;  r[7] = E0 - O0;
    r[1] = E1 + O1;  r[6] = E1 - O1;
    r[2] = E2 + O2;  r[5] = E2 - O2;
    r[3] = E3 + O3;  r[4] = E3 - O3;
}

__device__ __forceinline__ float4 luma4(float4 b, float4 g, float4 r) {
    float4 y;
    y.x = 0.114f * b.x + 0.587f * g.x + 0.299f * r.x;
    y.y = 0.114f * b.y + 0.587f * g.y + 0.299f * r.y;
    y.z = 0.114f * b.z + 0.587f * g.z + 0.299f * r.z;
    y.w = 0.114f * b.w + 0.587f * g.w + 0.299f * r.w;
    return y;
}

__global__ __launch_bounds__(128, 9)
void h264_dct_kernel(const float* __restrict__ x, float* __restrict__ out) {
    // CTA: 128 threads, strip = 8 rows x 128 cols = 16 8x8 blocks.
    // Load/store: thread owns 2 row-quads (rows r and r+4, cols 4*c4..) ->
    //   6 LDG.128 in / 6 STG.128 out (MLP_p1=6, minimizes L1tex-queue spread);
    //   bgr quads register-resident for the epilogue.
    // Transform: thread owns one column-of-8; register butterflies; one
    //   padded transpose buffer with exclusive-ownership write-back.
    __shared__ float yL[8][128];  // 512B row stride: quad AND column access
                                  // both bank-conflict-free
    __shared__ float t1[8][129];  // transpose buffer
    __shared__ float sQ[8][9];    // quant step
    __shared__ float sRQ[8][9];   // 1 / (q + 1e-8)

    const int t = threadIdx.x;
    if (t < 64) {
        int k = t >> 3, u = t & 7;
        // QF=28 >= 25 -> scale = 144 ; q = max(base*144/50, 1)
        float q = fmaxf((c_qbase[t] * 144.0f) / 50.0f, 1.0f);
        sQ[k][u]  = q;
        sRQ[k][u] = 1.0f / (q + 1e-8f);
    }

    // ---- Load phase: thread -> quads (r, c4) and (r+4, c4) ----
    const int r  = t >> 5;        // 0..3
    const int c4 = t & 31;        // 0..31
    const size_t base = (size_t)blockIdx.z * (3 * (size_t)PLANE)
                      + (size_t)(blockIdx.y * 8 + r) * IMG_W
                      + blockIdx.x * 128 + c4 * 4;
    const size_t row4 = (size_t)4 * IMG_W;

    const float4 vb0 = *reinterpret_cast<const float4*>(x + base);
    const float4 vb1 = *reinterpret_cast<const float4*>(x + base + row4);
    const float4 vg0 = *reinterpret_cast<const float4*>(x + base + PLANE);
    const float4 vg1 = *reinterpret_cast<const float4*>(x + base + PLANE + row4);
    const float4 vr0 = *reinterpret_cast<const float4*>(x + base + 2 * PLANE);
    const float4 vr1 = *reinterpret_cast<const float4*>(x + base + 2 * PLANE + row4);

    *reinterpret_cast<float4*>(&yL[r][c4 * 4])     = luma4(vb0, vg0, vr0);
    *reinterpret_cast<float4*>(&yL[r + 4][c4 * 4]) = luma4(vb1, vg1, vr1);
    __syncthreads();   // B1: luma tile + quant tables published

    // ---- Transform phase: thread owns column t ----
    const int g = t >> 3;         // block index
    const int l = t & 7;          // lane within block
    float a[8], w[8];

    #pragma unroll
    for (int i = 0; i < 8; ++i) a[i] = yL[i][t];   // bank t%32: conflict-free
    dct8(a, w);
    #pragma unroll
    for (int k = 0; k < 8; ++k) t1[k][t] = w[k];
    __syncthreads();   // B2

    // Row of block (cells exclusively owned by this thread)
    #pragma unroll
    for (int j = 0; j < 8; ++j) a[j] = t1[l][(g << 3) + j];
    dct8(a, w);
    float cq[8];
    #pragma unroll
    for (int u = 0; u < 8; ++u)
        cq[u] = rintf(w[u] * sRQ[l][u]) * sQ[l][u];   // round-half-even
    idct8(cq, w);
    #pragma unroll
    for (int b = 0; b < 8; ++b) t1[l][(g << 3) + b] = w[b];  // same cells
    __syncthreads();   // B3

    #pragma unroll
    for (int i = 0; i < 8; ++i) a[i] = t1[i][t];
    float rec[8];
    idct8(a, rec);
    #pragma unroll
    for (int i = 0; i < 8; ++i) yL[i][t] = rec[i];   // luma reads all done (< B2)
    __syncthreads();   // B4

    // ---- Epilogue: back to quad ownership ----
    const float4 rec0 = *reinterpret_cast<const float4*>(&yL[r][c4 * 4]);
    const float4 rec1 = *reinterpret_cast<const float4*>(&yL[r + 4][c4 * 4]);

    const float4 y0 = luma4(vb0, vg0, vr0);   // bitwise same as load phase
    const float4 y1 = luma4(vb1, vg1, vr1);

    float4 ob, og, orr;
    float yd;
    #define EPI(c, RQ, YQ, VB, VG, VR)                                   \
        yd = RQ.c - YQ.c;                                                \
        ob.c  = fminf(fmaxf(VB.c + 0.114f * yd, 0.0f), 255.0f);          \
        og.c  = fminf(fmaxf(VG.c + 0.587f * yd, 0.0f), 255.0f);          \
        orr.c = fminf(fmaxf(VR.c + 0.299f * yd, 0.0f), 255.0f);

    EPI(x, rec0, y0, vb0, vg0, vr0) EPI(y, rec0, y0, vb0, vg0, vr0)
    EPI(z, rec0, y0, vb0, vg0, vr0) EPI(w, rec0, y0, vb0, vg0, vr0)
    *reinterpret_cast<float4*>(out + base)             = ob;
    *reinterpret_cast<float4*>(out + base + PLANE)     = og;
    *reinterpret_cast<float4*>(out + base + 2 * PLANE) = orr;

    EPI(x, rec1, y1, vb1, vg1, vr1) EPI(y, rec1, y1, vb1, vg1, vr1)
    EPI(z, rec1, y1, vb1, vg1, vr1) EPI(w, rec1, y1, vb1, vg1, vr1)
    *reinterpret_cast<float4*>(out + base + row4)             = ob;
    *reinterpret_cast<float4*>(out + base + PLANE + row4)     = og;
    *reinterpret_cast<float4*>(out + base + 2 * PLANE + row4) = orr;
    #undef EPI
}

extern "C" void kernel_launch(void* const* d_in, const int* in_sizes, int n_in,
                              void* d_out, int out_size) {
    const float* x = (const float*)d_in[0];
    float* out = (float*)d_out;

    int B = in_sizes[0] / (3 * PLANE);

    dim3 block(128, 1, 1);
    dim3 grid(IMG_W / 128, IMG_H / 8, B);   // 15 x 135 x B
    h264_dct_kernel<<<grid, block>>>(x, out);
}